// round 15
// baseline (speedup 1.0000x reference)
#include <cuda_runtime.h>

// involution: out[b, g*64+c, h, w] = sum_{kh,kw} x[b, g*64+c, h+kh-3, w+kw-3] * wt[b,g,kh,kw,h,w]
// B=8, G=8, CPG=64, H=W=64, K=7, pad=3, stride=1.
// 2x2 tile split across a lane pair (s = tid&1): s=0 owns window rows 0..3, s=1 rows 4..7
// (walked in reverse, r = slot ^ 7s, so slot0 is single-set for both halves -> uniform code).
// 98 weight regs/thread -> 256-thread blocks at <=128 regs -> 16 warps/SM.
// smem word = global col + 4 (halo words permanent zero); cp.async.16; 8-buffer pipeline.

#define NTHREADS 256
#define TH 8
#define ROWS 14
#define SMW 80
#define PLANE (ROWS * SMW)     // 1120 floats / channel
#define NBUF 8

__device__ __forceinline__ unsigned long long pk2(float lo, float hi) {
    unsigned long long r;
    asm("mov.b64 %0, {%1, %2};" : "=l"(r) : "f"(lo), "f"(hi));
    return r;
}
__device__ __forceinline__ unsigned long long ffma2(unsigned long long a,
                                                    unsigned long long b,
                                                    unsigned long long c) {
    unsigned long long d;
    asm("fma.rn.f32x2 %0, %1, %2, %3;" : "=l"(d) : "l"(a), "l"(b), "l"(c));
    return d;
}
__device__ __forceinline__ float f2lo(unsigned long long v) {
    float a, b;
    asm("mov.b64 {%0, %1}, %2;" : "=f"(a), "=f"(b) : "l"(v));
    return a;
}
__device__ __forceinline__ float f2hi(unsigned long long v) {
    float a, b;
    asm("mov.b64 {%0, %1}, %2;" : "=f"(a), "=f"(b) : "l"(v));
    return b;
}
__device__ __forceinline__ void cp_async16(unsigned dst, const void* src) {
    asm volatile("cp.async.cg.shared.global [%0], [%1], 16;" :: "r"(dst), "l"(src));
}
__device__ __forceinline__ void cp_commit() {
    asm volatile("cp.async.commit_group;");
}
__device__ __forceinline__ void cp_wait4() {
    asm volatile("cp.async.wait_group 4;");
}

__global__ void __launch_bounds__(NTHREADS, 2) involution_kernel(
    const float* __restrict__ x, const float* __restrict__ wt, float* __restrict__ out)
{
    __shared__ __align__(16) float sbuf[NBUF * PLANE];   // 35840 B

    const int tid = threadIdx.x;
    const int bid = blockIdx.x;
    const int ht = bid & 7;
    const int g  = (bid >> 3) & 7;
    const int b  = bid >> 6;
    const int h0 = ht * TH;
    const int s  = tid & 1;            // tap-half
    const int u  = (tid >> 1) & 31;    // w-pair 0..31
    const int hq = tid >> 6;           // 0..3 -> h-pair
    const int ha = h0 + 2 * hq;
    const int wa = 2 * u;

    unsigned sbase;
    {
        unsigned long long t;
        asm("cvta.to.shared.u64 %0, %1;" : "=l"(t) : "l"((const void*)sbuf));
        sbase = (unsigned)t;
    }

    // zero everything once: w-halo words + h-OOB rows stay zero forever
    for (int i = tid; i < NBUF * PLANE; i += NTHREADS) sbuf[i] = 0.0f;

    // ---- weight sets. Set(h,kh): even-out uses taps t0..t6, odd-out u0..u6 of (h,kh,:,wa..wa+1).
    //   E = {(t1,t2),(t3,t4),(t5,t6)} on Q1,Q2,Q3; O = {(u0,u1),(u2,u3),(u4,u5)}; S = (t0,u6) on (rowp[1],rowp[8]).
    // U[j] applied to accX at slot j (row r = j ^ 7s):
    //   s=0: U[j] = Set(ha,   kh=j)       -> Apart;  s=1: U[j] = Set(ha+1, kh=6-j) -> Bpart
    // V[j-1] applied to accY at slots j=1..3:
    //   s=0: V     = Set(ha+1, kh=j-1)    -> Bpart;  s=1: V     = Set(ha,   kh=7-j) -> Apart
    const float* wgbase = wt + ((b * 8 + g) * 49) * 4096;
    const int hU = ha + s;
    const int hV = ha + 1 - s;
    unsigned long long UE[4][3], UO[4][3], US[4];
    unsigned long long VE[3][3], VO[3][3], VS[3];
#pragma unroll
    for (int j = 0; j < 4; j++) {
        const int kh = s ? (6 - j) : j;
        const float* wrow = wgbase + kh * 7 * 4096 + hU * 64 + wa;
        float we[7], wo[7];
#pragma unroll
        for (int kw = 0; kw < 7; kw++) {
            float2 p = *(const float2*)(wrow + kw * 4096);
            we[kw] = p.x; wo[kw] = p.y;
        }
        UE[j][0] = pk2(we[1], we[2]); UE[j][1] = pk2(we[3], we[4]); UE[j][2] = pk2(we[5], we[6]);
        UO[j][0] = pk2(wo[0], wo[1]); UO[j][1] = pk2(wo[2], wo[3]); UO[j][2] = pk2(wo[4], wo[5]);
        US[j]    = pk2(we[0], wo[6]);
    }
#pragma unroll
    for (int j = 1; j < 4; j++) {
        const int kh = s ? (7 - j) : (j - 1);
        const float* wrow = wgbase + kh * 7 * 4096 + hV * 64 + wa;
        float we[7], wo[7];
#pragma unroll
        for (int kw = 0; kw < 7; kw++) {
            float2 p = *(const float2*)(wrow + kw * 4096);
            we[kw] = p.x; wo[kw] = p.y;
        }
        VE[j-1][0] = pk2(we[1], we[2]); VE[j-1][1] = pk2(we[3], we[4]); VE[j-1][2] = pk2(we[5], we[6]);
        VO[j-1][0] = pk2(wo[0], wo[1]); VO[j-1][1] = pk2(wo[2], wo[3]); VO[j-1][2] = pk2(wo[4], wo[5]);
        VS[j-1]    = pk2(we[0], wo[6]);
    }

    // row offsets within the 8-row window: r = slot ^ 7s
    int roff[4];
#pragma unroll
    for (int j = 0; j < 4; j++) roff[j] = (j ^ (7 * s)) * SMW;

    // ---- cp.async slot: 224 x 16B interior chunks, 1 per thread
    unsigned sd0; int go0; bool p0;
    {
        int r0 = tid >> 4, c0 = tid & 15;
        sd0 = (unsigned)((r0 * SMW + 4 + c0 * 4) * 4);
        go0 = (h0 - 3 + r0) * 64 + c0 * 4;
        p0 = (tid < 224) && (h0 - 3 + r0 >= 0) && (h0 - 3 + r0 < 64);
    }

    const float* xg = x + ((b * 8 + g) * 64) * 4096;
    float* ogp = out + ((b * 8 + g) * 64) * 4096 + (ha + s) * 64 + wa;

    __syncthreads();   // zero-fill visible before any cp.async lands

    // ---- prologue: channels 0..3
#pragma unroll
    for (int pre = 0; pre < 4; pre++) {
        if (p0) cp_async16(sbase + (unsigned)(pre * PLANE * 4) + sd0, xg + pre * 4096 + go0);
        cp_commit();
    }

#pragma unroll 1
    for (int i = 0; i < 32; i++) {
        const int c0ch = 2 * i;
#pragma unroll
        for (int q = 0; q < 2; q++) {
            int cl = c0ch + 4 + q;
            if (cl < 64 && p0)
                cp_async16(sbase + (unsigned)(((cl & 7) * PLANE) * 4) + sd0, xg + cl * 4096 + go0);
            cp_commit();
        }
        cp_wait4();
        __syncthreads();

#pragma unroll
        for (int q = 0; q < 2; q++) {
            const int c = c0ch + q;
            const float* base = sbuf + (c & 7) * PLANE + (2 * hq) * SMW + wa;
            unsigned long long XE = 0, XO = 0, XS = 0, YE = 0, YO = 0, YS = 0;
#pragma unroll
            for (int slot = 0; slot < 4; slot++) {
                const float* rowp = base + roff[slot];
                unsigned long long Q1 = *(const unsigned long long*)(rowp + 2);
                unsigned long long Q2 = *(const unsigned long long*)(rowp + 4);
                unsigned long long Q3 = *(const unsigned long long*)(rowp + 6);
                unsigned long long SV = pk2(rowp[1], rowp[8]);
                XE = ffma2(Q1, UE[slot][0], XE);
                XO = ffma2(Q1, UO[slot][0], XO);
                XE = ffma2(Q2, UE[slot][1], XE);
                XO = ffma2(Q2, UO[slot][1], XO);
                XE = ffma2(Q3, UE[slot][2], XE);
                XO = ffma2(Q3, UO[slot][2], XO);
                XS = ffma2(SV, US[slot], XS);
                if (slot > 0) {
                    YE = ffma2(Q1, VE[slot-1][0], YE);
                    YO = ffma2(Q1, VO[slot-1][0], YO);
                    YE = ffma2(Q2, VE[slot-1][1], YE);
                    YO = ffma2(Q2, VO[slot-1][1], YO);
                    YE = ffma2(Q3, VE[slot-1][2], YE);
                    YO = ffma2(Q3, VO[slot-1][2], YO);
                    YS = ffma2(SV, VS[slot-1], YS);
                }
            }
            float xe = f2lo(XE) + f2hi(XE) + f2lo(XS);
            float xo = f2lo(XO) + f2hi(XO) + f2hi(XS);
            float ye = f2lo(YE) + f2hi(YE) + f2lo(YS);
            float yo = f2lo(YO) + f2hi(YO) + f2hi(YS);
            // partner (lane^1) holds the other half of MY output row's taps in its Y accumulator
            float pe = __shfl_xor_sync(0xffffffffu, ye, 1);
            float po = __shfl_xor_sync(0xffffffffu, yo, 1);
            *(float2*)(ogp + c * 4096) = make_float2(xe + pe, xo + po);
        }
    }
}

extern "C" void kernel_launch(void* const* d_in, const int* in_sizes, int n_in,
                              void* d_out, int out_size) {
    const float* x  = (const float*)d_in[0];
    const float* wt = (const float*)d_in[1];
    if (n_in >= 2 && in_sizes[0] == 8 * 8 * 7 * 7 * 64 * 64) {
        const float* t = x; x = wt; wt = t;
    }
    float* out = (float*)d_out;
    involution_kernel<<<512, NTHREADS>>>(x, wt, out);
}